// round 7
// baseline (speedup 1.0000x reference)
#include <cuda_runtime.h>
#include <math.h>

#define VOCABN 30000
#define DN 100
#define RN 150
#define RWN 50
#define SN 50
#define CN 20
#define BN 256
#define LN 512
#define VPB 60
#define WRS_STRIDE 152   // padded row stride for g_WrsT (16B-aligned rows)

typedef unsigned long long ull;

// ---- folded constants / tables (static device memory) ----
__device__ float g_Tv[VOCABN * RN];    // blended V embedding per vocab id
__device__ float g_Trw[VOCABN * SN];   // (Tv*Cvs)@Wrs1 + bs1 per vocab id
__device__ float g_Cvs[RN];
__device__ float g_wild[SN * SN];      // [s][t]
__device__ float g_S2cT[RN * SN];      // S2[t][r]*Cvs[r], stored [r][t]
__device__ float g_SC[CN * 200];       // [c][0:150]=C_embed*u | [c][150:200]=C_w*uw
__device__ float g_eT[RN * DN];        // embed_r transposed [r][d] (400B rows, aligned)
__device__ float g_WrsT[SN * WRS_STRIDE];  // Wrs1 transposed [s][r], padded rows

// ---- packed f32x2 helpers ----
__device__ __forceinline__ ull FMA2(ull a, ull b, ull c) {
    ull d;
    asm("fma.rn.f32x2 %0, %1, %2, %3;" : "=l"(d) : "l"(a), "l"(b), "l"(c));
    return d;
}
__device__ __forceinline__ float HSUM2(ull a, ull b) {
    union { ull u; float2 f; } x, y;
    x.u = a; y.u = b;
    return (x.f.x + x.f.y) + (y.f.x + y.f.y);
}
__device__ __forceinline__ ull PACK2(float a, float b) {
    union { ull u; float2 f; } x;
    x.f = make_float2(a, b);
    return x.u;
}

// 50-length dot: activations from 16B-aligned shared (SoA), weights as 25
// register-resident packed pairs. 12 LDS.128 + 1 LDS.64 + 25 fma.f32x2.
__device__ __forceinline__ float dot50(const float* __restrict__ a,
                                       const ull* __restrict__ w) {
    ull acc0 = 0ull, acc1 = 0ull;
#pragma unroll
    for (int j = 0; j < 6; j++) {
        ulonglong2 v0 = *(const ulonglong2*)(a + 8 * j);
        ulonglong2 v1 = *(const ulonglong2*)(a + 8 * j + 4);
        acc0 = FMA2(w[4 * j + 0], v0.x, acc0);
        acc1 = FMA2(w[4 * j + 1], v0.y, acc1);
        acc0 = FMA2(w[4 * j + 2], v1.x, acc0);
        acc1 = FMA2(w[4 * j + 3], v1.y, acc1);
    }
    ull t = *(const ull*)(a + 48);
    acc0 = FMA2(w[24], t, acc0);
    return HSUM2(acc0, acc1);
}

// ---------------------------------------------------------------------------
// k0: fold step-invariant constants + emit transposes. grid=32, block=256.
// Every block recomputes the tiny vectors; fills a slice of the big arrays.
// ---------------------------------------------------------------------------
__global__ void k0_const(const float* __restrict__ C_embed,
                         const float* __restrict__ C_w,
                         const float* __restrict__ S1w,
                         const float* __restrict__ S2w,
                         const float* __restrict__ WW,
                         const float* __restrict__ hT,
                         const float* __restrict__ S2,
                         const float* __restrict__ embed_r,
                         const float* __restrict__ Wrs1) {
    __shared__ float cvs[RN], cw[RWN], u[RN], uw[RWN];
    int t = threadIdx.x;
    if (t < RN) {
        float s = 0.f;
#pragma unroll
        for (int c = 0; c < CN; c++) s += C_embed[c * RN + t];
        cvs[t] = s;
        float su = 0.f;
#pragma unroll
        for (int s2 = 0; s2 < SN; s2++) su += hT[s2] * S2[s2 * RN + t];
        u[t] = su;
    }
    if (t < RWN) {
        float s = 0.f;
#pragma unroll
        for (int c = 0; c < CN; c++) s += C_w[c * RWN + t];
        cw[t] = s;
        float su = 0.f;
#pragma unroll
        for (int s2 = 0; s2 < SN; s2++) su += hT[s2] * S2w[s2 * RWN + t];
        uw[t] = su;
    }
    __syncthreads();

    const int N_CVS = RN;                     // 150
    const int N_WLD = SN * SN;                // 2500
    const int N_S2C = RN * SN;                // 7500
    const int N_SC  = CN * 200;               // 4000
    const int N_ET  = RN * DN;                // 15000
    const int N_WT  = SN * WRS_STRIDE;        // 7600 (padded)
    const int TOT = N_CVS + N_WLD + N_S2C + N_SC + N_ET + N_WT;
    int stride = gridDim.x * blockDim.x;
    for (int g = blockIdx.x * blockDim.x + t; g < TOT; g += stride) {
        int i = g;
        if (i < N_CVS) { g_Cvs[i] = cvs[i]; continue; }
        i -= N_CVS;
        if (i < N_WLD) {
            int s = i / SN, tt = i % SN;
            float acc = WW[i];
#pragma unroll
            for (int r = 0; r < RWN; r++)
                acc += S1w[s * RWN + r] * cw[r] * S2w[tt * RWN + r];
            g_wild[i] = acc;
            continue;
        }
        i -= N_WLD;
        if (i < N_S2C) {
            int r = i / SN, tt = i % SN;
            g_S2cT[i] = S2[tt * RN + r] * cvs[r];
            continue;
        }
        i -= N_S2C;
        if (i < N_SC) {
            int c = i / 200, k = i % 200;
            g_SC[i] = (k < RN) ? C_embed[c * RN + k] * u[k]
                               : C_w[c * RWN + (k - RN)] * uw[k - RN];
            continue;
        }
        i -= N_SC;
        if (i < N_ET) {
            int r = i / DN, d = i % DN;
            g_eT[i] = embed_r[d * RN + r];
            continue;
        }
        i -= N_ET;
        {
            int s = i / WRS_STRIDE, r = i % WRS_STRIDE;
            g_WrsT[i] = (r < RN) ? Wrs1[r * SN + s] : 0.f;  // zero pad tail
        }
    }
}

// ---------------------------------------------------------------------------
// k1: per-vocab tables. grid=500, block=160, 60 vocab rows per block.
// Transposed weights -> contiguous LDG.128 per thread, L1-resident across
// the 60 rows. tanh.approx.f32 for the nonlinearity.
// ---------------------------------------------------------------------------
__global__ void __launch_bounds__(160)
k1_tables(const float* __restrict__ W_embed,
          const float* __restrict__ V_embed,
          const float* __restrict__ beta,
          const float* __restrict__ bs1) {
    __shared__ __align__(16) float w[DN];
    __shared__ __align__(16) float q[152];   // padded so float4 reads are safe
    int t = threadIdx.x;
    int v0 = blockIdx.x * VPB;
    if (t < 2) q[150 + t] = 0.f;

    for (int vi = 0; vi < VPB; vi++) {
        int v = v0 + vi;
        if (t < DN) w[t] = W_embed[v * DN + t];
        __syncthreads();
        if (t < RN) {
            const float* er = &g_eT[t * DN];      // 400B rows: 16B aligned
            float a0 = 0.f, a1 = 0.f, a2 = 0.f, a3 = 0.f;
#pragma unroll
            for (int j = 0; j < 25; j++) {
                float4 e = *(const float4*)(er + 4 * j);
                float4 ww = *(const float4*)(w + 4 * j);
                a0 += e.x * ww.x; a1 += e.y * ww.y;
                a2 += e.z * ww.z; a3 += e.w * ww.w;
            }
            float acc = (a0 + a1) + (a2 + a3);
            float th;
            asm("tanh.approx.f32 %0, %1;" : "=f"(th) : "f"(acc));
            float b = beta[t];
            float tv = V_embed[v * RN + t] * b + th * (1.f - b);
            g_Tv[v * RN + t] = tv;
            q[t] = tv * g_Cvs[t];
        }
        __syncthreads();
        if (t < SN) {
            const float* wr = &g_WrsT[t * WRS_STRIDE];  // 608B rows: 16B aligned
            float a0 = 0.f, a1 = 0.f, a2 = 0.f, a3 = 0.f;
#pragma unroll
            for (int j = 0; j < 38; j++) {              // 152 = 38 * 4 (pad is 0)
                float4 ww = *(const float4*)(wr + 4 * j);
                float4 qq = *(const float4*)(q + 4 * j);
                a0 += ww.x * qq.x;
                a1 += ww.y * qq.y;
                a2 += ww.z * qq.z;
                a3 += ww.w * qq.w;
            }
            g_Trw[v * SN + t] = bs1[t] + (a0 + a1) + (a2 + a3);
        }
        __syncthreads();
    }
}

// ---------------------------------------------------------------------------
// k2: sequential recurrence. 128 CTAs x 288 threads, 2 batch chains per CTA
// (SoA: act_x / act_y). Weights register-resident as packed f32x2 pairs.
//
// Shared float layout (16B-aligned bases):
//   hbuf0 @   0  (50)   hbuf1 @  64 (50)     <- double-buffered state
//   p0 @ 128   p1 @ 192   p2 @ 256 (50 ea)   <- (h@S1)*Tv chunks
//   aw @ 320  (50)                           <- h@S1_w
//
// Step = phase1 (dots over h) -> bar -> phase2 (chunk dots + warp-shuffle
// 4:1 reduce + h/out writeback + next-step gather prefetch) -> bar.
// ---------------------------------------------------------------------------
__global__ void __launch_bounds__(288, 1)
k2_recur(const int* __restrict__ tokens,
         const float* __restrict__ S1,
         const float* __restrict__ S1w,
         const float* __restrict__ Wss1,
         const float* __restrict__ h0,
         const float* __restrict__ prio_a,
         const float* __restrict__ prio_b,
         float* __restrict__ out) {
    __shared__ __align__(16) float act_x[384];
    __shared__ __align__(16) float act_y[384];
    __shared__ float2 gz[SN];
    __shared__ int s_ntok[2];

    int t = threadIdx.x;
    int b0 = blockIdx.x * 2;
    int b1 = b0 + 1;
    int tb0 = b0 * LN, tb1 = b1 * LN;
    long ob0 = (long)b0 * LN * CN, ob1 = (long)b1 * LN * CN;

    // ---- phase-1 weights (packed pairs over k) ----
    ull wAp[25];
    int p1w = 0;
    if (t < 150) {
#pragma unroll
        for (int j = 0; j < 25; j++)
            wAp[j] = PACK2(S1[(2 * j) * RN + t], S1[(2 * j + 1) * RN + t]);
        p1w = 128 + (t / 50) * 64 + (t % 50);
    } else if (t < 200) {
        int rw = t - 150;
#pragma unroll
        for (int j = 0; j < 25; j++)
            wAp[j] = PACK2(S1w[(2 * j) * RWN + rw], S1w[(2 * j + 1) * RWN + rw]);
    } else if (t < 250) {
        int s2 = t - 200;
#pragma unroll
        for (int j = 0; j < 25; j++)
            wAp[j] = PACK2(Wss1[(2 * j) * SN + s2], Wss1[(2 * j + 1) * SN + s2]);
    } else {
#pragma unroll
        for (int j = 0; j < 25; j++) wAp[j] = 0ull;
    }

    // ---- phase-2 weights ----
    ull wBp[25];
    int aoff = 0;
    bool useHc = false;   // wild chunk reads the live h buffer (parity-swapped)
    if (t < 200) {
        int tt = t >> 2, q = t & 3;
        if (q < 3) {
#pragma unroll
            for (int j = 0; j < 25; j++)
                wBp[j] = PACK2(g_S2cT[(q * 50 + 2 * j) * SN + tt],
                               g_S2cT[(q * 50 + 2 * j + 1) * SN + tt]);
            aoff = 128 + 64 * q;
        } else {
#pragma unroll
            for (int j = 0; j < 25; j++)
                wBp[j] = PACK2(g_wild[(2 * j) * SN + tt],
                               g_wild[(2 * j + 1) * SN + tt]);
            useHc = true;
        }
    } else if (t < 280) {
        int m = t - 200, c = m >> 2, q = m & 3;
        int base = c * 200 + (q < 3 ? q * 50 : 150);
#pragma unroll
        for (int j = 0; j < 25; j++)
            wBp[j] = PACK2(g_SC[base + 2 * j], g_SC[base + 2 * j + 1]);
        aoff = (q < 3) ? 128 + 64 * q : 320;
    } else {
#pragma unroll
        for (int j = 0; j < 25; j++) wBp[j] = 0ull;  // dummy (uniform shuffles)
        aoff = 0;
    }

    float pa = 0.f, pb = 0.f;
    if (t >= 200 && t < 280 && (t & 3) == 0) {
        int c = (t - 200) >> 2;
        pa = prio_a[c]; pb = prio_b[c];
    }

    // ---- init: state + prime step-0 gathers ----
    if (t < SN) { float h = h0[t]; act_x[t] = h; act_y[t] = h; }
    float tvx = 0.f, tvy = 0.f, trx = 0.f, tryy = 0.f;
    {
        int t0 = tokens[tb0], t1 = tokens[tb1];
        if (t < 150) { tvx = g_Tv[t0 * RN + t]; tvy = g_Tv[t1 * RN + t]; }
        if (t >= 200 && t < 250) {
            int s2 = t - 200;
            trx  = g_Trw[t0 * SN + s2];
            tryy = g_Trw[t1 * SN + s2];
        }
    }
    __syncthreads();

    for (int l = 0; l < LN; l++) {
        int hc = (l & 1) ? 64 : 0;

        // ---------------- phase 1: dots over h ----------------
        if (t < 250) {
            float ax = dot50(act_x + hc, wAp);
            float ay = dot50(act_y + hc, wAp);
            if (t < 150) {
                act_x[p1w] = ax * tvx;
                act_y[p1w] = ay * tvy;
            } else if (t < 200) {
                act_x[320 + (t - 150)] = ax;
                act_y[320 + (t - 150)] = ay;
            } else {
                float zx = 1.f / (1.f + __expf(-(ax + trx)));
                float zy = 1.f / (1.f + __expf(-(ay + tryy)));
                gz[t - 200] = make_float2(zx, zy);
            }
        } else if (t == 280) {
            int nl = (l + 1 < LN) ? l + 1 : l;
            s_ntok[0] = tokens[tb0 + nl];
        } else if (t == 281) {
            int nl = (l + 1 < LN) ? l + 1 : l;
            s_ntok[1] = tokens[tb1 + nl];
        }
        __syncthreads();

        // -------- phase 2: chunk dots + reduce + writeback + prefetch -------
        {
            int n0 = s_ntok[0], n1 = s_ntok[1];
            if (t < 150) {
                tvx = g_Tv[n0 * RN + t];
                tvy = g_Tv[n1 * RN + t];
            } else if (t >= 200 && t < 250) {
                int s2 = t - 200;
                trx  = g_Trw[n0 * SN + s2];
                tryy = g_Trw[n1 * SN + s2];
            }

            int a2 = useHc ? hc : aoff;
            float sx = dot50(act_x + a2, wBp);
            float sy = dot50(act_y + a2, wBp);

            sx += __shfl_xor_sync(0xffffffffu, sx, 1);
            sx += __shfl_xor_sync(0xffffffffu, sx, 2);
            sy += __shfl_xor_sync(0xffffffffu, sy, 1);
            sy += __shfl_xor_sync(0xffffffffu, sy, 2);

            if ((t & 3) == 0 && t < 280) {
                if (t < 200) {
                    int tt = t >> 2;
                    int hn = 64 - hc;
                    float2 z = gz[tt];
                    float hox = act_x[hc + tt], hoy = act_y[hc + tt];
                    act_x[hn + tt] = z.x * sx + (1.f - z.x) * hox;
                    act_y[hn + tt] = z.y * sy + (1.f - z.y) * hoy;
                } else {
                    int c = (t - 200) >> 2;
                    out[ob0 + (long)l * CN + c] = sx * pa + pb;
                    out[ob1 + (long)l * CN + c] = sy * pa + pb;
                }
            }
        }
        __syncthreads();
    }
}

// ---------------------------------------------------------------------------
// Launch. Inputs (metadata order): tokens, W_embed, embed_r, V_embed,
// C_embed, S1, S2, S1_w, S2_w, C_w, WW, h0, hT, beta_vec, Wss1, Wrs1, bs1,
// prio_a, prio_b
// ---------------------------------------------------------------------------
extern "C" void kernel_launch(void* const* d_in, const int* in_sizes, int n_in,
                              void* d_out, int out_size) {
    const int*   tokens  = (const int*)  d_in[0];
    const float* W_embed = (const float*)d_in[1];
    const float* embed_r = (const float*)d_in[2];
    const float* V_embed = (const float*)d_in[3];
    const float* C_embed = (const float*)d_in[4];
    const float* S1      = (const float*)d_in[5];
    const float* S2      = (const float*)d_in[6];
    const float* S1_w    = (const float*)d_in[7];
    const float* S2_w    = (const float*)d_in[8];
    const float* C_w     = (const float*)d_in[9];
    const float* WW      = (const float*)d_in[10];
    const float* h0      = (const float*)d_in[11];
    const float* hT      = (const float*)d_in[12];
    const float* beta    = (const float*)d_in[13];
    const float* Wss1    = (const float*)d_in[14];
    const float* Wrs1    = (const float*)d_in[15];
    const float* bs1     = (const float*)d_in[16];
    const float* prio_a  = (const float*)d_in[17];
    const float* prio_b  = (const float*)d_in[18];
    float* out = (float*)d_out;

    k0_const<<<32, 256>>>(C_embed, C_w, S1_w, S2_w, WW, hT, S2, embed_r, Wrs1);
    k1_tables<<<VOCABN / VPB, 160>>>(W_embed, V_embed, beta, bs1);
    k2_recur<<<BN / 2, 288>>>(tokens, S1, S1_w, Wss1, h0, prio_a, prio_b, out);
}

// round 8
// speedup vs baseline: 2.1917x; 2.1917x over previous
#include <cuda_runtime.h>
#include <math.h>

#define VOCABN 30000
#define DN 100
#define RN 150
#define RWN 50
#define SN 50
#define CN 20
#define BN 256
#define LN 512
#define VR 4            // vocab rows per k1 block
#define WIN 68          // k2 shared window stride in floats (272B: 16B-aligned,
                        // 272 mod 128 = 16 -> adjacent windows on distinct banks)

typedef unsigned long long ull;

// ---- folded constants / tables (static device memory) ----
__device__ float g_Tv[VOCABN * RN];    // blended V embedding per vocab id
__device__ float g_Trw[VOCABN * SN];   // (Tv*Cvs)@Wrs1 + bs1 per vocab id
__device__ float g_Cvs[RN];
__device__ float g_wild[SN * SN];      // [s][t]
__device__ float g_S2cT[RN * SN];      // S2[t][r]*Cvs[r], stored [r][t]
__device__ float g_SC[CN * 200];       // [c][0:150]=C_embed*u | [c][150:200]=C_w*uw

// ---- packed f32x2 helpers ----
__device__ __forceinline__ ull FMA2(ull a, ull b, ull c) {
    ull d;
    asm("fma.rn.f32x2 %0, %1, %2, %3;" : "=l"(d) : "l"(a), "l"(b), "l"(c));
    return d;
}
__device__ __forceinline__ float HSUM2(ull a, ull b) {
    union { ull u; float2 f; } x, y;
    x.u = a; y.u = b;
    return (x.f.x + x.f.y) + (y.f.x + y.f.y);
}
__device__ __forceinline__ ull PACK2(float a, float b) {
    union { ull u; float2 f; } x;
    x.f = make_float2(a, b);
    return x.u;
}

// 50-length dot: activations from 16B-aligned shared (SoA), weights as 25
// register-resident packed pairs. 12 LDS.128 + 1 LDS.64 + 25 fma.f32x2.
__device__ __forceinline__ float dot50(const float* __restrict__ a,
                                       const ull* __restrict__ w) {
    ull acc0 = 0ull, acc1 = 0ull;
#pragma unroll
    for (int j = 0; j < 6; j++) {
        ulonglong2 v0 = *(const ulonglong2*)(a + 8 * j);
        ulonglong2 v1 = *(const ulonglong2*)(a + 8 * j + 4);
        acc0 = FMA2(w[4 * j + 0], v0.x, acc0);
        acc1 = FMA2(w[4 * j + 1], v0.y, acc1);
        acc0 = FMA2(w[4 * j + 2], v1.x, acc0);
        acc1 = FMA2(w[4 * j + 3], v1.y, acc1);
    }
    ull t = *(const ull*)(a + 48);
    acc0 = FMA2(w[24], t, acc0);
    return HSUM2(acc0, acc1);
}

// ---------------------------------------------------------------------------
// k0: fold step-invariant constants. grid=32, block=256.
// ---------------------------------------------------------------------------
__global__ void k0_const(const float* __restrict__ C_embed,
                         const float* __restrict__ C_w,
                         const float* __restrict__ S1w,
                         const float* __restrict__ S2w,
                         const float* __restrict__ WW,
                         const float* __restrict__ hT,
                         const float* __restrict__ S2) {
    __shared__ float cvs[RN], cw[RWN], u[RN], uw[RWN];
    int t = threadIdx.x;
    if (t < RN) {
        float s = 0.f;
#pragma unroll
        for (int c = 0; c < CN; c++) s += C_embed[c * RN + t];
        cvs[t] = s;
        float su = 0.f;
#pragma unroll
        for (int s2 = 0; s2 < SN; s2++) su += hT[s2] * S2[s2 * RN + t];
        u[t] = su;
    }
    if (t < RWN) {
        float s = 0.f;
#pragma unroll
        for (int c = 0; c < CN; c++) s += C_w[c * RWN + t];
        cw[t] = s;
        float su = 0.f;
#pragma unroll
        for (int s2 = 0; s2 < SN; s2++) su += hT[s2] * S2w[s2 * RWN + t];
        uw[t] = su;
    }
    __syncthreads();

    const int N_CVS = RN;                 // 150
    const int N_WLD = SN * SN;            // 2500
    const int N_S2C = RN * SN;            // 7500
    const int N_SC  = CN * 200;           // 4000
    const int TOT = N_CVS + N_WLD + N_S2C + N_SC;
    int stride = gridDim.x * blockDim.x;
    for (int g = blockIdx.x * blockDim.x + t; g < TOT; g += stride) {
        int i = g;
        if (i < N_CVS) { g_Cvs[i] = cvs[i]; continue; }
        i -= N_CVS;
        if (i < N_WLD) {
            int s = i / SN, tt = i % SN;
            float acc = WW[i];
#pragma unroll
            for (int r = 0; r < RWN; r++)
                acc += S1w[s * RWN + r] * cw[r] * S2w[tt * RWN + r];
            g_wild[i] = acc;
            continue;
        }
        i -= N_WLD;
        if (i < N_S2C) {
            int r = i / SN, tt = i % SN;
            g_S2cT[i] = S2[tt * RN + r] * cvs[r];
            continue;
        }
        i -= N_S2C;
        {
            int c = i / 200, k = i % 200;
            g_SC[i] = (k < RN) ? C_embed[c * RN + k] * u[k]
                               : C_w[c * RWN + (k - RN)] * uw[k - RN];
        }
    }
}

// ---------------------------------------------------------------------------
// k1: per-vocab tables. grid=7500 (4 rows/block), block=160.
// Each embed_r element read once feeds 4 accumulators (4x less L2 traffic).
// All loads scalar + coalesced; W rows broadcast from shared.
// ---------------------------------------------------------------------------
__global__ void __launch_bounds__(160)
k1_tables(const float* __restrict__ W_embed,
          const float* __restrict__ embed_r,
          const float* __restrict__ V_embed,
          const float* __restrict__ beta,
          const float* __restrict__ Wrs1,
          const float* __restrict__ bs1) {
    __shared__ float w4[VR * DN];    // 4 consecutive W_embed rows
    __shared__ float q4[VR][RN];     // tv * Cvs per row
    int t = threadIdx.x;
    int v0 = blockIdx.x * VR;

    for (int i = t; i < VR * DN; i += 160)
        w4[i] = W_embed[v0 * DN + i];          // contiguous rows -> coalesced
    __syncthreads();

    if (t < RN) {
        float a0 = 0.f, a1 = 0.f, a2 = 0.f, a3 = 0.f;
#pragma unroll 4
        for (int d = 0; d < DN; d++) {
            float e = embed_r[d * RN + t];     // coalesced, L2-resident
            a0 += e * w4[0 * DN + d];          // broadcast LDS
            a1 += e * w4[1 * DN + d];
            a2 += e * w4[2 * DN + d];
            a3 += e * w4[3 * DN + d];
        }
        float cv = g_Cvs[t];
        float b = beta[t];
        float acc[VR] = {a0, a1, a2, a3};
#pragma unroll
        for (int r = 0; r < VR; r++) {
            float th;
            asm("tanh.approx.f32 %0, %1;" : "=f"(th) : "f"(acc[r]));
            float tv = V_embed[(v0 + r) * RN + t] * b + th * (1.f - b);
            g_Tv[(v0 + r) * RN + t] = tv;
            q4[r][t] = tv * cv;
        }
    }
    __syncthreads();

    if (t < SN) {
        float a0 = 0.f, a1 = 0.f, a2 = 0.f, a3 = 0.f;
#pragma unroll 2
        for (int d = 0; d < RN; d++) {
            float wv = Wrs1[d * SN + t];       // coalesced, L2-resident
            a0 += wv * q4[0][d];
            a1 += wv * q4[1][d];
            a2 += wv * q4[2][d];
            a3 += wv * q4[3][d];
        }
        float bb = bs1[t];
        g_Trw[(v0 + 0) * SN + t] = bb + a0;
        g_Trw[(v0 + 1) * SN + t] = bb + a1;
        g_Trw[(v0 + 2) * SN + t] = bb + a2;
        g_Trw[(v0 + 3) * SN + t] = bb + a3;
    }
}

// ---------------------------------------------------------------------------
// k2: sequential recurrence. 128 CTAs x 288 threads, 2 batch chains per CTA
// (SoA: act_x / act_y). Weights register-resident as packed f32x2 pairs.
//
// Shared windows (stride WIN=68 floats = 272B; all bases 16B-aligned and
// pairwise-distinct mod 128B -> conflict-free 16B accesses across roles):
//   hbuf0 @ 0     hbuf1 @ 68           <- double-buffered state
//   p0 @ 136   p1 @ 204   p2 @ 272     <- (h@S1)*Tv chunks
//   aw @ 340                           <- h@S1_w
//
// Step = phase1 (dots over h) -> bar -> phase2 (chunk dots + warp-shuffle
// 4:1 reduce + h/out writeback + next-step gather prefetch) -> bar.
// ---------------------------------------------------------------------------
__global__ void __launch_bounds__(288, 1)
k2_recur(const int* __restrict__ tokens,
         const float* __restrict__ S1,
         const float* __restrict__ S1w,
         const float* __restrict__ Wss1,
         const float* __restrict__ h0,
         const float* __restrict__ prio_a,
         const float* __restrict__ prio_b,
         float* __restrict__ out) {
    __shared__ __align__(16) float act_x[6 * WIN];
    __shared__ __align__(16) float act_y[6 * WIN];
    __shared__ float2 gz[SN];
    __shared__ int s_ntok[2];

    int t = threadIdx.x;
    int b0 = blockIdx.x * 2;
    int b1 = b0 + 1;
    int tb0 = b0 * LN, tb1 = b1 * LN;
    long ob0 = (long)b0 * LN * CN, ob1 = (long)b1 * LN * CN;

    // ---- phase-1 weights (packed pairs over k) ----
    ull wAp[25];
    int p1w = 0;
    if (t < 150) {
#pragma unroll
        for (int j = 0; j < 25; j++)
            wAp[j] = PACK2(S1[(2 * j) * RN + t], S1[(2 * j + 1) * RN + t]);
        p1w = 2 * WIN + (t / 50) * WIN + (t % 50);
    } else if (t < 200) {
        int rw = t - 150;
#pragma unroll
        for (int j = 0; j < 25; j++)
            wAp[j] = PACK2(S1w[(2 * j) * RWN + rw], S1w[(2 * j + 1) * RWN + rw]);
    } else if (t < 250) {
        int s2 = t - 200;
#pragma unroll
        for (int j = 0; j < 25; j++)
            wAp[j] = PACK2(Wss1[(2 * j) * SN + s2], Wss1[(2 * j + 1) * SN + s2]);
    } else {
#pragma unroll
        for (int j = 0; j < 25; j++) wAp[j] = 0ull;
    }

    // ---- phase-2 weights ----
    ull wBp[25];
    int aoff = 0;
    bool useHc = false;   // wild chunk reads the live h buffer (parity-swapped)
    if (t < 200) {
        int tt = t >> 2, q = t & 3;
        if (q < 3) {
#pragma unroll
            for (int j = 0; j < 25; j++)
                wBp[j] = PACK2(g_S2cT[(q * 50 + 2 * j) * SN + tt],
                               g_S2cT[(q * 50 + 2 * j + 1) * SN + tt]);
            aoff = 2 * WIN + WIN * q;
        } else {
#pragma unroll
            for (int j = 0; j < 25; j++)
                wBp[j] = PACK2(g_wild[(2 * j) * SN + tt],
                               g_wild[(2 * j + 1) * SN + tt]);
            useHc = true;
        }
    } else if (t < 280) {
        int m = t - 200, c = m >> 2, q = m & 3;
        int base = c * 200 + (q < 3 ? q * 50 : 150);
#pragma unroll
        for (int j = 0; j < 25; j++)
            wBp[j] = PACK2(g_SC[base + 2 * j], g_SC[base + 2 * j + 1]);
        aoff = (q < 3) ? 2 * WIN + WIN * q : 5 * WIN;
    } else {
#pragma unroll
        for (int j = 0; j < 25; j++) wBp[j] = 0ull;  // dummy (uniform shuffles)
        aoff = 0;
    }

    float pa = 0.f, pb = 0.f;
    if (t >= 200 && t < 280 && (t & 3) == 0) {
        int c = (t - 200) >> 2;
        pa = prio_a[c]; pb = prio_b[c];
    }

    // ---- init: state + prime step-0 gathers ----
    if (t < SN) { float h = h0[t]; act_x[t] = h; act_y[t] = h; }
    float tvx = 0.f, tvy = 0.f, trx = 0.f, tryy = 0.f;
    {
        int t0 = tokens[tb0], t1 = tokens[tb1];
        if (t < 150) { tvx = g_Tv[t0 * RN + t]; tvy = g_Tv[t1 * RN + t]; }
        if (t >= 200 && t < 250) {
            int s2 = t - 200;
            trx  = g_Trw[t0 * SN + s2];
            tryy = g_Trw[t1 * SN + s2];
        }
    }
    __syncthreads();

    for (int l = 0; l < LN; l++) {
        int hc = (l & 1) ? WIN : 0;

        // ---------------- phase 1: dots over h ----------------
        if (t < 250) {
            float ax = dot50(act_x + hc, wAp);
            float ay = dot50(act_y + hc, wAp);
            if (t < 150) {
                act_x[p1w] = ax * tvx;
                act_y[p1w] = ay * tvy;
            } else if (t < 200) {
                act_x[5 * WIN + (t - 150)] = ax;
                act_y[5 * WIN + (t - 150)] = ay;
            } else {
                float zx = 1.f / (1.f + __expf(-(ax + trx)));
                float zy = 1.f / (1.f + __expf(-(ay + tryy)));
                gz[t - 200] = make_float2(zx, zy);
            }
        } else if (t == 280) {
            int nl = (l + 1 < LN) ? l + 1 : l;
            s_ntok[0] = tokens[tb0 + nl];
        } else if (t == 281) {
            int nl = (l + 1 < LN) ? l + 1 : l;
            s_ntok[1] = tokens[tb1 + nl];
        }
        __syncthreads();

        // -------- phase 2: chunk dots + reduce + writeback + prefetch -------
        {
            int n0 = s_ntok[0], n1 = s_ntok[1];
            if (t < 150) {
                tvx = g_Tv[n0 * RN + t];
                tvy = g_Tv[n1 * RN + t];
            } else if (t >= 200 && t < 250) {
                int s2 = t - 200;
                trx  = g_Trw[n0 * SN + s2];
                tryy = g_Trw[n1 * SN + s2];
            }

            int a2 = useHc ? hc : aoff;
            float sx = dot50(act_x + a2, wBp);
            float sy = dot50(act_y + a2, wBp);

            sx += __shfl_xor_sync(0xffffffffu, sx, 1);
            sx += __shfl_xor_sync(0xffffffffu, sx, 2);
            sy += __shfl_xor_sync(0xffffffffu, sy, 1);
            sy += __shfl_xor_sync(0xffffffffu, sy, 2);

            if ((t & 3) == 0 && t < 280) {
                if (t < 200) {
                    int tt = t >> 2;
                    int hn = WIN - hc;
                    float2 z = gz[tt];
                    float hox = act_x[hc + tt], hoy = act_y[hc + tt];
                    act_x[hn + tt] = z.x * sx + (1.f - z.x) * hox;
                    act_y[hn + tt] = z.y * sy + (1.f - z.y) * hoy;
                } else {
                    int c = (t - 200) >> 2;
                    out[ob0 + (long)l * CN + c] = sx * pa + pb;
                    out[ob1 + (long)l * CN + c] = sy * pa + pb;
                }
            }
        }
        __syncthreads();
    }
}

// ---------------------------------------------------------------------------
// Launch. Inputs (metadata order): tokens, W_embed, embed_r, V_embed,
// C_embed, S1, S2, S1_w, S2_w, C_w, WW, h0, hT, beta_vec, Wss1, Wrs1, bs1,
// prio_a, prio_b
// ---------------------------------------------------------------------------
extern "C" void kernel_launch(void* const* d_in, const int* in_sizes, int n_in,
                              void* d_out, int out_size) {
    const int*   tokens  = (const int*)  d_in[0];
    const float* W_embed = (const float*)d_in[1];
    const float* embed_r = (const float*)d_in[2];
    const float* V_embed = (const float*)d_in[3];
    const float* C_embed = (const float*)d_in[4];
    const float* S1      = (const float*)d_in[5];
    const float* S2      = (const float*)d_in[6];
    const float* S1_w    = (const float*)d_in[7];
    const float* S2_w    = (const float*)d_in[8];
    const float* C_w     = (const float*)d_in[9];
    const float* WW      = (const float*)d_in[10];
    const float* h0      = (const float*)d_in[11];
    const float* hT      = (const float*)d_in[12];
    const float* beta    = (const float*)d_in[13];
    const float* Wss1    = (const float*)d_in[14];
    const float* Wrs1    = (const float*)d_in[15];
    const float* bs1     = (const float*)d_in[16];
    const float* prio_a  = (const float*)d_in[17];
    const float* prio_b  = (const float*)d_in[18];
    float* out = (float*)d_out;

    k0_const<<<32, 256>>>(C_embed, C_w, S1_w, S2_w, WW, hT, S2);
    k1_tables<<<VOCABN / VR, 160>>>(W_embed, embed_r, V_embed, beta, Wrs1, bs1);
    k2_recur<<<BN / 2, 288>>>(tokens, S1, S1_w, Wss1, h0, prio_a, prio_b, out);
}